// round 16
// baseline (speedup 1.0000x reference)
#include <cuda_runtime.h>

#define H   64
#define NH  4
#define MA  64
#define BS  64
#define E   256    // H*NH
#define MAXROWS 4096

// scratch (device globals: no allocation allowed)
// P layout for E-vectors: element e (l=e&31, k=e>>5) stored at
//   p = (k>>2)*128 + 4*l + (k&3)
// -> lane l's 8 elements are two float4s at quads l and 32+l (conflict-free LDS).
__device__ float g_u[MAXROWS * E];
__device__ float g_p[MAXROWS * 4];       // p_r[n] = sum_{e==n mod 4} ws[e]*u_r[e]
__device__ float g_csum[BS * MA * E];    // csum rows, P layout
__device__ float g_molpart[BS * 4 * H];
__device__ int   g_count[BS];

__device__ __forceinline__ long long scope_at(const void* sp, int i, bool is64) {
    return is64 ? ((const long long*)sp)[i] : (long long)((const int*)sp)[i];
}
__device__ __forceinline__ bool scope_is64(const void* sp) {
    // scope flat: [1, 2, ...]; int32 -> word1 == 2 ; int64 -> word1 == 0
    return ((const int*)sp)[1] == 0;
}
__device__ __forceinline__ unsigned long long pack2(float x) {
    unsigned r = __float_as_uint(x);
    unsigned long long o;
    asm("mov.b64 %0, {%1, %1};" : "=l"(o) : "r"(r));
    return o;
}
#define FMA2(acc, a, b) asm("fma.rn.f32x2 %0, %1, %2, %0;" : "+l"(acc) : "l"(a), "l"(b))

// ---------------------------------------------------------------------------
// Kernel A: u = inputs @ Wa_pair (all N+1 flat rows), P-layout store,
// plus p_r[n] head-sums (for the abs-identity score). Zeroes flat row 0 and
// arrival counters.
// dyn smem: wa_s[64*256] + cs[16*64] = 68 KB (stage reuses wa_s after loop)
// ---------------------------------------------------------------------------
__global__ void __launch_bounds__(256) kA(const float* __restrict__ inputs,
                                          const float* __restrict__ Wa_pair,
                                          const float* __restrict__ Wa_score,
                                          int n1, float* __restrict__ d_out) {
    extern __shared__ float sm[];
    float* wa_s = sm;            // 64 x 256
    float* cs   = sm + H * E;    // 16 x 64
    const int t = threadIdx.x, blk = blockIdx.x;

    if (blk == 0) {
        if (t < 16)                             // flat row 0 = pad row
            ((float4*)(d_out + BS * H))[t] = make_float4(0.f, 0.f, 0.f, 0.f);
        if (t < BS) g_count[t] = 0;
    }

#pragma unroll
    for (int it = 0; it < 16; it++)
        ((float4*)wa_s)[t + 256 * it] = __ldg(((const float4*)Wa_pair) + t + 256 * it);

    {
        int r = blk * 16 + (t >> 4), q = t & 15;
        float4 z = make_float4(0.f, 0.f, 0.f, 0.f);
        ((float4*)cs)[t] = (r < n1) ? ((const float4*)(inputs + (size_t)r * H))[q] : z;
    }
    __syncthreads();

    const int eg = t & 63, rg = t >> 6;   // 4 e-cols (quad e0 = heads of h=eg), 4 rows
    const int e0 = eg * 4;
    float4 acc[4];
#pragma unroll
    for (int m = 0; m < 4; m++) acc[m] = make_float4(0.f, 0.f, 0.f, 0.f);

#pragma unroll 4
    for (int h = 0; h < H; h++) {
        float4 w = *(const float4*)(wa_s + h * E + e0);
#pragma unroll
        for (int m = 0; m < 4; m++) {
            float c = cs[(rg * 4 + m) * H + h];
            acc[m].x = fmaf(c, w.x, acc[m].x);
            acc[m].y = fmaf(c, w.y, acc[m].y);
            acc[m].z = fmaf(c, w.z, acc[m].z);
            acc[m].w = fmaf(c, w.w, acc[m].w);
        }
    }

    // P-layout store of u
#pragma unroll
    for (int m = 0; m < 4; m++) {
        int rr = blk * 16 + rg * 4 + m;
        if (rr < n1) {
            float* dst = g_u + (size_t)rr * E;
            float a4[4] = {acc[m].x, acc[m].y, acc[m].z, acc[m].w};
#pragma unroll
            for (int c = 0; c < 4; c++) {
                int e = e0 + c;
                int l = e & 31, k = e >> 5;
                dst[(k >> 2) * 128 + 4 * l + (k & 3)] = a4[c];
            }
        }
    }

    // ---- p_r[n] = sum over h of ws[h*4+n]*u_r[h*4+n] ----
    __syncthreads();                 // wa_s dead -> reuse as stage[rmn][eg], stride 65
    float* stage = wa_s;             // 64 x 65 floats
    {
        float4 wsq = __ldg((const float4*)(Wa_score + e0));   // heads 0..3 of h=eg
#pragma unroll
        for (int m = 0; m < 4; m++) {
            int base = (rg * 16 + m * 4) * 65 + eg;
            stage[base]            = wsq.x * acc[m].x;
            stage[base + 65]       = wsq.y * acc[m].y;
            stage[base + 2 * 65]   = wsq.z * acc[m].z;
            stage[base + 3 * 65]   = wsq.w * acc[m].w;
        }
    }
    __syncthreads();
    if (t < 64) {
        int r = t >> 2, n = t & 3;               // local row, head
        const float* row = stage + ((r >> 2) * 16 + (r & 3) * 4 + n) * 65;
        float s = 0.f;
#pragma unroll
        for (int e4 = 0; e4 < 64; e4++) s += row[e4];
        int rr = blk * 16 + r;
        if (rr < n1) g_p[rr * 4 + n] = s;
    }
}

// ---------------------------------------------------------------------------
// Kernel B: pairwise attention + c_sum -> g_csum (P layout).
// grid (64, 4): (mol, i-quarter). 256 threads = 8 warps, 2 i per warp.
// Score via abs identity: s = 0.5*(p_i + p_j + sum ws*|u_i+u_j|); the linear
// halves are precomputed (g_p), killing 16 FMNMX per j-step.
// dyn smem: u_s[64*256] + c_s[64*64] + p_s[64*4] = 81 KB -> 2 blocks/SM.
// NO launch_bounds cap: body wants ~90 regs; a 64-reg cap spills (R6/R9/R11/R12).
// ---------------------------------------------------------------------------
__global__ void kB(const void* __restrict__ scope,
                   const float* __restrict__ inputs,
                   const float* __restrict__ Wa_score) {
    extern __shared__ float sm[];
    float* u_s = sm;                 // 64 rows x 256 (P layout)
    float* c_s = sm + MA * E;        // 64 rows x 64 (quad-swizzled)
    float* p_s = c_s + MA * H;       // 64 rows x 4

    const bool is64 = scope_is64(scope);
    const int b = blockIdx.x, qq = blockIdx.y;
    const int t = threadIdx.x, l = t & 31, wid = t >> 5;
    const int n = l & 3;

    // lane l owns e = l + 32k  (head n = l&3 lane-constant -> 3-shuffle reduce)
    float ws[8];
#pragma unroll
    for (int k = 0; k < 8; k++) ws[k] = __ldg(Wa_score + l + 32 * k);

    // own 2 i-rows of u straight from gmem (P layout rows)
    const int i0 = qq * 16 + wid, i1 = i0 + 8;
    long long sIA = scope_at(scope, b * MA + i0, is64);
    long long sIB = scope_at(scope, b * MA + i1, is64);
    const float4* uA = (const float4*)(g_u + (size_t)sIA * E);
    const float4* uB = (const float4*)(g_u + (size_t)sIB * E);
    float4 A0 = __ldg(uA + l), A1 = __ldg(uA + 32 + l);
    float4 B0 = __ldg(uB + l), B1 = __ldg(uB + 32 + l);
    float pA025 = 0.25f * __ldg(g_p + sIA * 4 + n);
    float pB025 = 0.25f * __ldg(g_p + sIB * 4 + n);

    // stage u tile: 64 rows x 64 quads = 4096 float4
#pragma unroll
    for (int it = 0; it < 16; it++) {
        int Q = t + 256 * it;
        int j = Q >> 6, qd = Q & 63;
        long long s = scope_at(scope, b * MA + j, is64);
        ((float4*)u_s)[Q] = ((const float4*)(g_u + (size_t)s * E))[qd];
    }
    // stage c tile: 64 rows x 16 quads, quad-swizzled
#pragma unroll
    for (int it = 0; it < 4; it++) {
        int Q = t + 256 * it;
        int j = Q >> 4, qd = Q & 15;
        long long s = scope_at(scope, b * MA + j, is64);
        const float* src = inputs + (size_t)s * H;
        int h = qd >> 1;
        int mb = ((qd & 1) == (qd >> 3)) ? 0 : 4;
        float4 v;
        v.x = src[h + 8 * (mb + 0)];
        v.y = src[h + 8 * (mb + 1)];
        v.z = src[h + 8 * (mb + 2)];
        v.w = src[h + 8 * (mb + 3)];
        ((float4*)c_s)[Q] = v;
    }
    // stage p tile (64 rows x 4)
    if (t < 64) {
        long long s = scope_at(scope, b * MA + t, is64);
        ((float4*)p_s)[t] = __ldg((const float4*)(g_p + s * 4));
    }
    __syncthreads();

    const int hq = l >> 2;
    const int qA = 2 * hq + (hq >> 2);       // h>=4 -> +1
    const int qB = 2 * hq + 1 - (hq >> 2);

    unsigned long long csA[4] = {0, 0, 0, 0}, csB[4] = {0, 0, 0, 0};

#pragma unroll 2
    for (int j = 0; j < MA; j++) {
        const float4* ur = (const float4*)(u_s + j * E);
        float4 a0 = ur[l], a1 = ur[32 + l];
        float pj = p_s[j * 4 + n];
        float v, sA0, sA1, sB0, sB1;
        v = A0.x + a0.x; sA0 = fabsf(v) * ws[0];
        v = A0.y + a0.y; sA1 = fabsf(v) * ws[1];
        v = A0.z + a0.z; sA0 = fmaf(fabsf(v), ws[2], sA0);
        v = A0.w + a0.w; sA1 = fmaf(fabsf(v), ws[3], sA1);
        v = A1.x + a1.x; sA0 = fmaf(fabsf(v), ws[4], sA0);
        v = A1.y + a1.y; sA1 = fmaf(fabsf(v), ws[5], sA1);
        v = A1.z + a1.z; sA0 = fmaf(fabsf(v), ws[6], sA0);
        v = A1.w + a1.w; sA1 = fmaf(fabsf(v), ws[7], sA1);

        v = B0.x + a0.x; sB0 = fabsf(v) * ws[0];
        v = B0.y + a0.y; sB1 = fabsf(v) * ws[1];
        v = B0.z + a0.z; sB0 = fmaf(fabsf(v), ws[2], sB0);
        v = B0.w + a0.w; sB1 = fmaf(fabsf(v), ws[3], sB1);
        v = B1.x + a1.x; sB0 = fmaf(fabsf(v), ws[4], sB0);
        v = B1.y + a1.y; sB1 = fmaf(fabsf(v), ws[5], sB1);
        v = B1.z + a1.z; sB0 = fmaf(fabsf(v), ws[6], sB0);
        v = B1.w + a1.w; sB1 = fmaf(fabsf(v), ws[7], sB1);

        float sA = sA0 + sA1, sB = sB0 + sB1;
        sA += __shfl_xor_sync(0xffffffffu, sA, 4);
        sB += __shfl_xor_sync(0xffffffffu, sB, 4);
        sA += __shfl_xor_sync(0xffffffffu, sA, 8);
        sB += __shfl_xor_sync(0xffffffffu, sB, 8);
        sA += __shfl_xor_sync(0xffffffffu, sA, 16);
        sB += __shfl_xor_sync(0xffffffffu, sB, 16);

        // sigmoid(s_full), s_full = 0.5*(p_i + p_j + sum|.|) ; tanh arg = 0.25*(...)
        float argA = fmaf(0.25f, sA, fmaf(0.25f, pj, pA025));
        float argB = fmaf(0.25f, sB, fmaf(0.25f, pj, pB025));
        float tA, tB;
        asm("tanh.approx.f32 %0, %1;" : "=f"(tA) : "f"(argA));
        asm("tanh.approx.f32 %0, %1;" : "=f"(tB) : "f"(argB));
        unsigned long long attA = pack2(fmaf(0.5f, tA, 0.5f));
        unsigned long long attB = pack2(fmaf(0.5f, tB, 0.5f));

        ulonglong2 c01 = *(const ulonglong2*)(c_s + j * H + 4 * qA);
        ulonglong2 c23 = *(const ulonglong2*)(c_s + j * H + 4 * qB);
        FMA2(csA[0], attA, c01.x);  FMA2(csA[1], attA, c01.y);
        FMA2(csA[2], attA, c23.x);  FMA2(csA[3], attA, c23.y);
        FMA2(csB[0], attB, c01.x);  FMA2(csB[1], attB, c01.y);
        FMA2(csB[2], attB, c23.x);  FMA2(csB[3], attB, c23.y);
    }

    // store csum rows in P layout: lane l -> quads l and 32+l
    {
        ulonglong2 v;
        float* oA = g_csum + (size_t)(b * MA + i0) * E;
        v.x = csA[0]; v.y = csA[1]; *(ulonglong2*)(oA + 4 * l) = v;
        v.x = csA[2]; v.y = csA[3]; *(ulonglong2*)(oA + 128 + 4 * l) = v;
        float* oB = g_csum + (size_t)(b * MA + i1) * E;
        v.x = csB[0]; v.y = csB[1]; *(ulonglong2*)(oB + 4 * l) = v;
        v.x = csB[2]; v.y = csB[3]; *(ulonglong2*)(oB + 128 + 4 * l) = v;
    }
}

// ---------------------------------------------------------------------------
// Kernel D: projection A = csum @ Wp, scatter flat, molecule partials +
// deterministic last-block c_mol (counter scheme, fixed-order sum).
// grid (64, 4): (mol, quarter), 16 rows/block -> 256 blocks (2x SM coverage).
// dyn smem: wp_s[256*64] (P-permuted rows) + cs_s[16*256] = 80 KB.
// ---------------------------------------------------------------------------
__global__ void __launch_bounds__(256) kD(const void* __restrict__ scope,
                                          const float* __restrict__ Wp,
                                          float* __restrict__ d_out) {
    extern __shared__ float sm[];
    float* wp_s = sm;            // 256 x 64, row p holds Wp row e(p)
    float* cs_s = sm + E * H;    // 16 x 256 (P layout)
    __shared__ int flag;

    const bool is64 = scope_is64(scope);
    const int m = blockIdx.x, q = blockIdx.y;
    const int t = threadIdx.x;

    // stage Wp P-permuted: p -> e = (r>>2) + 32*((r&3) + 4*(p>>7)), r = p&127
#pragma unroll
    for (int it = 0; it < 16; it++) {
        int qd = t + 256 * it;
        int p = qd >> 4, quad = qd & 15;
        int hf = p >> 7, r = p & 127;
        int e = (r >> 2) + 32 * ((r & 3) + 4 * hf);
        ((float4*)wp_s)[qd] = __ldg(((const float4*)Wp) + e * 16 + quad);
    }
    // stage 16 csum rows (contiguous, layout matches wp_s)
    {
        const float4* src = (const float4*)(g_csum + (size_t)(m * MA + q * 16) * E);
#pragma unroll
        for (int it = 0; it < 4; it++) ((float4*)cs_s)[t + 256 * it] = src[t + 256 * it];
    }
    __syncthreads();

    const int cg = t & 15, rg = t >> 4;   // 16 col-groups x 16 rows
    const int c0 = cg * 4;
    unsigned long long acc01 = 0, acc23 = 0;
#pragma unroll 4
    for (int p = 0; p < E; p++) {
        ulonglong2 w = ((const ulonglong2*)wp_s)[p * 16 + cg];
        unsigned long long cc = pack2(cs_s[rg * E + p]);
        FMA2(acc01, cc, w.x);  FMA2(acc23, cc, w.y);
    }

    // scatter flat: flat[scope[m*64 + q*16 + rg]] = row  (scope==0 -> pad, skip)
    float* flat = d_out + BS * H;
    {
        long long s = scope_at(scope, m * MA + q * 16 + rg, is64);
        if (s > 0) {
            ulonglong2 o; o.x = acc01; o.y = acc23;
            *((ulonglong2*)(flat + s * H + c0)) = o;
        }
    }

    // molecule partial + deterministic last-block c_mol
    __syncthreads();                     // cs_s free -> 16x64 reduction buf
    {
        ulonglong2 o; o.x = acc01; o.y = acc23;
        *((ulonglong2*)(cs_s + rg * H + c0)) = o;
    }
    __syncthreads();
    if (t < H) {
        float s = 0.f;
#pragma unroll
        for (int g = 0; g < 16; g++) s += cs_s[g * H + t];
        g_molpart[(m * 4 + q) * H + t] = s;
        __threadfence();
    }
    __syncthreads();
    if (t == 0) {
        int old = atomicAdd(&g_count[m], 1);
        flag = (old == 3);
    }
    __syncthreads();
    if (flag && t < H) {
        __threadfence();
        const float* mp = g_molpart + m * 4 * H + t;
        d_out[m * H + t] = (mp[0] + mp[H]) + (mp[2 * H] + mp[3 * H]);
    }
}

// ---------------------------------------------------------------------------
extern "C" void kernel_launch(void* const* d_in, const int* in_sizes, int n_in,
                              void* d_out, int out_size) {
    const float* inputs   = (const float*)d_in[0];
    const void*  scope    = d_in[1];
    // d_in[2] = scope_rev_tensor (unused: scatter via scope is its inverse)
    const float* Wa_pair  = (const float*)d_in[3];
    const float* Wa_score = (const float*)d_in[4];
    const float* Wp       = (const float*)d_in[5];
    float* out = (float*)d_out;

    const int n1 = in_sizes[0] / H;                                   // N+1 flat rows
    const int smemA = (H * E + 16 * H) * (int)sizeof(float);          // 69632 B
    const int smemB = (MA * E + MA * H + MA * 4) * (int)sizeof(float);// 82944 B
    const int smemD = (E * H + 16 * E) * (int)sizeof(float);          // 81920 B
    cudaFuncSetAttribute(kA, cudaFuncAttributeMaxDynamicSharedMemorySize, smemA);
    cudaFuncSetAttribute(kB, cudaFuncAttributeMaxDynamicSharedMemorySize, smemB);
    cudaFuncSetAttribute(kD, cudaFuncAttributeMaxDynamicSharedMemorySize, smemD);

    kA<<<(n1 + 15) / 16, 256, smemA>>>(inputs, Wa_pair, Wa_score, n1, out);
    kB<<<dim3(BS, 4), 256, smemB>>>(scope, inputs, Wa_score);
    kD<<<dim3(BS, 4), 256, smemD>>>(scope, Wp, out);
}

// round 17
// speedup vs baseline: 1.1362x; 1.1362x over previous
#include <cuda_runtime.h>

#define H   64
#define NH  4
#define MA  64
#define BS  64
#define E   256    // H*NH
#define MAXROWS 4096

// scratch (device globals: no allocation allowed)
// P layout for E-vectors: element e (l=e&31, k=e>>5) stored at
//   p = (k>>2)*128 + 4*l + (k&3)
// -> lane l's 8 elements are two float4s at quads l and 32+l (conflict-free LDS).
__device__ float g_u[MAXROWS * E];
__device__ float g_csum[BS * MA * E];    // csum rows, P layout

__device__ __forceinline__ long long scope_at(const void* sp, int i, bool is64) {
    return is64 ? ((const long long*)sp)[i] : (long long)((const int*)sp)[i];
}
__device__ __forceinline__ bool scope_is64(const void* sp) {
    // scope flat: [1, 2, ...]; int32 -> word1 == 2 ; int64 -> word1 == 0
    return ((const int*)sp)[1] == 0;
}
__device__ __forceinline__ unsigned long long pack2(float x) {
    unsigned r = __float_as_uint(x);
    unsigned long long o;
    asm("mov.b64 %0, {%1, %1};" : "=l"(o) : "r"(r));
    return o;
}
#define FMA2(acc, a, b) asm("fma.rn.f32x2 %0, %1, %2, %0;" : "+l"(acc) : "l"(a), "l"(b))

// ---------------------------------------------------------------------------
// Kernel A: u = inputs @ Wa_pair (all N+1 flat rows), P-layout store.
// 16 rows/block, Wa_pair staged in smem. Zeroes c_mol region + flat row 0
// (kD accumulates c_mol with atomicAdd).
// dyn smem: wa_s[64*256] + cs[16*64] = 68 KB
// ---------------------------------------------------------------------------
__global__ void __launch_bounds__(256) kA(const float* __restrict__ inputs,
                                          const float* __restrict__ Wa_pair,
                                          int n1, float* __restrict__ d_out) {
    extern __shared__ float sm[];
    float* wa_s = sm;            // 64 x 256
    float* cs   = sm + H * E;    // 16 x 64
    const int t = threadIdx.x, blk = blockIdx.x;

    if (blk == 0) {
        float4 z = make_float4(0.f, 0.f, 0.f, 0.f);
#pragma unroll
        for (int it = 0; it < 4; it++)          // c_mol region: 4096 floats
            ((float4*)d_out)[t + 256 * it] = z;
        if (t < 16)                             // flat row 0 = pad row
            ((float4*)(d_out + BS * H))[t] = z;
    }

#pragma unroll
    for (int it = 0; it < 16; it++)
        ((float4*)wa_s)[t + 256 * it] = __ldg(((const float4*)Wa_pair) + t + 256 * it);

    {
        int r = blk * 16 + (t >> 4), q = t & 15;
        float4 z = make_float4(0.f, 0.f, 0.f, 0.f);
        ((float4*)cs)[t] = (r < n1) ? ((const float4*)(inputs + (size_t)r * H))[q] : z;
    }
    __syncthreads();

    const int eg = t & 63, rg = t >> 6;   // 4 e-cols, 4 rows per thread
    const int e0 = eg * 4;
    float4 acc[4];
#pragma unroll
    for (int m = 0; m < 4; m++) acc[m] = make_float4(0.f, 0.f, 0.f, 0.f);

#pragma unroll 4
    for (int h = 0; h < H; h++) {
        float4 w = *(const float4*)(wa_s + h * E + e0);
#pragma unroll
        for (int m = 0; m < 4; m++) {
            float c = cs[(rg * 4 + m) * H + h];
            acc[m].x = fmaf(c, w.x, acc[m].x);
            acc[m].y = fmaf(c, w.y, acc[m].y);
            acc[m].z = fmaf(c, w.z, acc[m].z);
            acc[m].w = fmaf(c, w.w, acc[m].w);
        }
    }

#pragma unroll
    for (int m = 0; m < 4; m++) {
        int rr = blk * 16 + rg * 4 + m;
        if (rr < n1) {
            float* dst = g_u + (size_t)rr * E;
            float a4[4] = {acc[m].x, acc[m].y, acc[m].z, acc[m].w};
#pragma unroll
            for (int c = 0; c < 4; c++) {
                int e = e0 + c;
                int l = e & 31, k = e >> 5;
                dst[(k >> 2) * 128 + 4 * l + (k & 3)] = a4[c];
            }
        }
    }
}

// ---------------------------------------------------------------------------
// Kernel B: pairwise attention + c_sum -> g_csum (P layout).
// grid (64, 4): (mol, i-quarter). 256 threads = 8 warps, 2 i per warp.
// Inner loop: explicit 4-j batches with PHASE-GROUPED shuffles (8 independent
// chains issue back-to-back per stage) to collapse the serial SHFL latency.
// dyn smem: u_s[64*256] + c_s[64*64] = 80 KB -> 2 blocks/SM.
// NO launch_bounds cap (64-reg caps spill; proven R6/R9/R11).
// ---------------------------------------------------------------------------
__global__ void kB(const void* __restrict__ scope,
                   const float* __restrict__ inputs,
                   const float* __restrict__ Wa_score) {
    extern __shared__ float sm[];
    float* u_s = sm;                 // 64 rows x 256 (P layout)
    float* c_s = sm + MA * E;        // 64 rows x 64 (quad-swizzled)

    const bool is64 = scope_is64(scope);
    const int b = blockIdx.x, qq = blockIdx.y;
    const int t = threadIdx.x, l = t & 31, wid = t >> 5;

    // lane l owns e = l + 32k  (head n = l&3 lane-constant -> 3-shuffle reduce)
    float ws[8];
#pragma unroll
    for (int k = 0; k < 8; k++) ws[k] = __ldg(Wa_score + l + 32 * k);

    // stage u tile: 64 rows x 64 quads = 4096 float4
#pragma unroll
    for (int it = 0; it < 16; it++) {
        int Q = t + 256 * it;
        int j = Q >> 6, qd = Q & 63;
        long long s = scope_at(scope, b * MA + j, is64);
        ((float4*)u_s)[Q] = ((const float4*)(g_u + (size_t)s * E))[qd];
    }
    // stage c tile: 64 rows x 16 quads, quad-swizzled
    // quad qd: h=qd>>1, holds m-range mb..mb+3 where mb=0 iff (qd&1)==(qd>>3)
#pragma unroll
    for (int it = 0; it < 4; it++) {
        int Q = t + 256 * it;
        int j = Q >> 4, qd = Q & 15;
        long long s = scope_at(scope, b * MA + j, is64);
        const float* src = inputs + (size_t)s * H;
        int h = qd >> 1;
        int mb = ((qd & 1) == (qd >> 3)) ? 0 : 4;
        float4 v;
        v.x = src[h + 8 * (mb + 0)];
        v.y = src[h + 8 * (mb + 1)];
        v.z = src[h + 8 * (mb + 2)];
        v.w = src[h + 8 * (mb + 3)];
        ((float4*)c_s)[Q] = v;
    }
    __syncthreads();

    const int hq = l >> 2;
    const int qA = 2 * hq + (hq >> 2);       // h>=4 -> +1
    const int qB = 2 * hq + 1 - (hq >> 2);
    const int i0 = qq * 16 + wid, i1 = i0 + 8;

    const float4* uiA = (const float4*)(u_s + i0 * E);
    float4 A0 = uiA[l], A1 = uiA[32 + l];
    const float4* uiB = (const float4*)(u_s + i1 * E);
    float4 B0 = uiB[l], B1 = uiB[32 + l];

    unsigned long long csA[4] = {0, 0, 0, 0}, csB[4] = {0, 0, 0, 0};

    for (int j0 = 0; j0 < MA; j0 += 4) {
        float sAv[4], sBv[4];

        // phase 1: 8 independent score chains
#pragma unroll
        for (int u = 0; u < 4; u++) {
            const float4* ur = (const float4*)(u_s + (j0 + u) * E);
            float4 a0 = ur[l], a1 = ur[32 + l];
            float v, s0, s1, r0, r1;
            v = fmaxf(A0.x + a0.x, 0.f); s0 = v * ws[0];
            v = fmaxf(A0.y + a0.y, 0.f); s1 = v * ws[1];
            v = fmaxf(A0.z + a0.z, 0.f); s0 = fmaf(v, ws[2], s0);
            v = fmaxf(A0.w + a0.w, 0.f); s1 = fmaf(v, ws[3], s1);
            v = fmaxf(A1.x + a1.x, 0.f); s0 = fmaf(v, ws[4], s0);
            v = fmaxf(A1.y + a1.y, 0.f); s1 = fmaf(v, ws[5], s1);
            v = fmaxf(A1.z + a1.z, 0.f); s0 = fmaf(v, ws[6], s0);
            v = fmaxf(A1.w + a1.w, 0.f); s1 = fmaf(v, ws[7], s1);

            v = fmaxf(B0.x + a0.x, 0.f); r0 = v * ws[0];
            v = fmaxf(B0.y + a0.y, 0.f); r1 = v * ws[1];
            v = fmaxf(B0.z + a0.z, 0.f); r0 = fmaf(v, ws[2], r0);
            v = fmaxf(B0.w + a0.w, 0.f); r1 = fmaf(v, ws[3], r1);
            v = fmaxf(B1.x + a1.x, 0.f); r0 = fmaf(v, ws[4], r0);
            v = fmaxf(B1.y + a1.y, 0.f); r1 = fmaf(v, ws[5], r1);
            v = fmaxf(B1.z + a1.z, 0.f); r0 = fmaf(v, ws[6], r0);
            v = fmaxf(B1.w + a1.w, 0.f); r1 = fmaf(v, ws[7], r1);
            sAv[u] = s0 + s1;
            sBv[u] = r0 + r1;
        }

        // phase 2: grouped butterfly stages (8 chains in flight per stage)
#pragma unroll
        for (int u = 0; u < 4; u++) {
            sAv[u] += __shfl_xor_sync(0xffffffffu, sAv[u], 4);
            sBv[u] += __shfl_xor_sync(0xffffffffu, sBv[u], 4);
        }
#pragma unroll
        for (int u = 0; u < 4; u++) {
            sAv[u] += __shfl_xor_sync(0xffffffffu, sAv[u], 8);
            sBv[u] += __shfl_xor_sync(0xffffffffu, sBv[u], 8);
        }
#pragma unroll
        for (int u = 0; u < 4; u++) {
            sAv[u] += __shfl_xor_sync(0xffffffffu, sAv[u], 16);
            sBv[u] += __shfl_xor_sync(0xffffffffu, sBv[u], 16);
        }

        // phase 3: grouped sigmoid (tanh form)
#pragma unroll
        for (int u = 0; u < 4; u++) {
            float tA, tB;
            asm("tanh.approx.f32 %0, %1;" : "=f"(tA) : "f"(0.5f * sAv[u]));
            asm("tanh.approx.f32 %0, %1;" : "=f"(tB) : "f"(0.5f * sBv[u]));
            sAv[u] = fmaf(0.5f, tA, 0.5f);
            sBv[u] = fmaf(0.5f, tB, 0.5f);
        }

        // phase 4: csum accumulation
#pragma unroll
        for (int u = 0; u < 4; u++) {
            unsigned long long attA = pack2(sAv[u]);
            unsigned long long attB = pack2(sBv[u]);
            const float* cr = c_s + (j0 + u) * H;
            ulonglong2 c01 = *(const ulonglong2*)(cr + 4 * qA);
            ulonglong2 c23 = *(const ulonglong2*)(cr + 4 * qB);
            FMA2(csA[0], attA, c01.x);  FMA2(csA[1], attA, c01.y);
            FMA2(csA[2], attA, c23.x);  FMA2(csA[3], attA, c23.y);
            FMA2(csB[0], attB, c01.x);  FMA2(csB[1], attB, c01.y);
            FMA2(csB[2], attB, c23.x);  FMA2(csB[3], attB, c23.y);
        }
    }

    // store csum rows in P layout: lane l -> quads l and 32+l
    {
        ulonglong2 v;
        float* oA = g_csum + (size_t)(b * MA + i0) * E;
        v.x = csA[0]; v.y = csA[1]; *(ulonglong2*)(oA + 4 * l) = v;
        v.x = csA[2]; v.y = csA[3]; *(ulonglong2*)(oA + 128 + 4 * l) = v;
        float* oB = g_csum + (size_t)(b * MA + i1) * E;
        v.x = csB[0]; v.y = csB[1]; *(ulonglong2*)(oB + 4 * l) = v;
        v.x = csB[2]; v.y = csB[3]; *(ulonglong2*)(oB + 128 + 4 * l) = v;
    }
}

// ---------------------------------------------------------------------------
// Kernel D: projection A = csum @ Wp, scatter flat rows, c_mol via atomicAdd.
// grid 128 = (b, half of 32 rows). 256 threads; thread = 2 rows x 4 cols.
// dyn smem: wp_s[256*64] (P-permuted rows) + cs_s[32*256] = 96 KB.
// ---------------------------------------------------------------------------
__global__ void __launch_bounds__(256) kD(const void* __restrict__ scope,
                                          const float* __restrict__ Wp,
                                          float* __restrict__ d_out) {
    extern __shared__ float sm[];
    float* wp_s = sm;            // 256 x 64, row p holds Wp row e(p)
    float* cs_s = sm + E * H;    // 32 x 256 (P layout)

    const bool is64 = scope_is64(scope);
    const int b = blockIdx.x >> 1, half = blockIdx.x & 1;
    const int t = threadIdx.x;

    // stage Wp P-permuted: p -> e = (r>>2) + 32*((r&3) + 4*(p>>7)), r = p&127
#pragma unroll
    for (int it = 0; it < 16; it++) {
        int q = t + 256 * it;            // 256 p * 16 quads
        int p = q >> 4, quad = q & 15;
        int hf = p >> 7, r = p & 127;
        int e = (r >> 2) + 32 * ((r & 3) + 4 * hf);
        ((float4*)wp_s)[q] = __ldg(((const float4*)Wp) + e * 16 + quad);
    }
    // stage 32 csum rows (contiguous copy; layout already matches wp_s)
    {
        const float4* src = (const float4*)(g_csum + (size_t)(b * MA + half * 32) * E);
#pragma unroll
        for (int it = 0; it < 8; it++) ((float4*)cs_s)[t + 256 * it] = src[t + 256 * it];
    }
    __syncthreads();

    const int cg = t & 15, rg = t >> 4;   // 16 col-groups x 16 row-groups
    const int c0 = cg * 4, r0 = rg * 2;
    unsigned long long accA01 = 0, accA23 = 0, accB01 = 0, accB23 = 0;

#pragma unroll 4
    for (int p = 0; p < E; p++) {
        ulonglong2 w = ((const ulonglong2*)wp_s)[p * 16 + cg];
        unsigned long long ca = pack2(cs_s[r0 * E + p]);
        unsigned long long cb = pack2(cs_s[(r0 + 1) * E + p]);
        FMA2(accA01, ca, w.x);  FMA2(accA23, ca, w.y);
        FMA2(accB01, cb, w.x);  FMA2(accB23, cb, w.y);
    }

    // scatter flat rows: flat[scope[b*64+r]] = A[b,r]  (scope==0 -> pad, skip)
    float* flat = d_out + BS * H;
    {
        int r = half * 32 + r0;
        long long s0 = scope_at(scope, b * MA + r, is64);
        long long s1 = scope_at(scope, b * MA + r + 1, is64);
        ulonglong2 vA; vA.x = accA01; vA.y = accA23;   // == float4 {c0..c3}
        ulonglong2 vB; vB.x = accB01; vB.y = accB23;
        if (s0 > 0) *((ulonglong2*)(flat + s0 * H + c0)) = vA;
        if (s1 > 0) *((ulonglong2*)(flat + s1 * H + c0)) = vB;
    }

    __syncthreads();                     // done reading cs_s -> reuse as reduction buf
    float* red = cs_s;                   // 16 x 64
    {
        unsigned long long s01, s23;
        asm("add.rn.f32x2 %0, %1, %2;" : "=l"(s01) : "l"(accA01), "l"(accB01));
        asm("add.rn.f32x2 %0, %1, %2;" : "=l"(s23) : "l"(accA23), "l"(accB23));
        ulonglong2 v; v.x = s01; v.y = s23;
        *((ulonglong2*)(red + rg * H + c0)) = v;
    }
    __syncthreads();
    if (t < H) {
        float s = 0.f;
#pragma unroll
        for (int g = 0; g < 16; g++) s += red[g * H + t];
        atomicAdd(d_out + b * H + t, s);   // exactly 2 contributors: deterministic
    }
}

// ---------------------------------------------------------------------------
extern "C" void kernel_launch(void* const* d_in, const int* in_sizes, int n_in,
                              void* d_out, int out_size) {
    const float* inputs   = (const float*)d_in[0];
    const void*  scope    = d_in[1];
    // d_in[2] = scope_rev_tensor (unused: scatter via scope is its inverse)
    const float* Wa_pair  = (const float*)d_in[3];
    const float* Wa_score = (const float*)d_in[4];
    const float* Wp       = (const float*)d_in[5];
    float* out = (float*)d_out;

    const int n1 = in_sizes[0] / H;                              // N+1 flat rows
    const int smemA = (H * E + 16 * H) * (int)sizeof(float);     // 69632 B
    const int smemB = (MA * E + MA * H) * (int)sizeof(float);    // 81920 B
    const int smemD = (E * H + 32 * E) * (int)sizeof(float);     // 98304 B
    cudaFuncSetAttribute(kA, cudaFuncAttributeMaxDynamicSharedMemorySize, smemA);
    cudaFuncSetAttribute(kB, cudaFuncAttributeMaxDynamicSharedMemorySize, smemB);
    cudaFuncSetAttribute(kD, cudaFuncAttributeMaxDynamicSharedMemorySize, smemD);

    kA<<<(n1 + 15) / 16, 256, smemA>>>(inputs, Wa_pair, n1, out);
    kB<<<dim3(BS, 4), 256, smemB>>>(scope, inputs, Wa_score);
    kD<<<BS * 2, 256, smemD>>>(scope, Wp, out);
}